// round 15
// baseline (speedup 1.0000x reference)
#include <cuda_runtime.h>
#include <cuda_fp16.h>
#include <math.h>
#include <stdint.h>

#define Bq    64
#define NEV   512
#define KDIM  128
#define HDIM  512
#define G7    3584
#define NCTA  128
#define NTH   256
#define GST   40            /* gsum row stride in floats */

// ---------------- SMEM layout (bytes, dynamic) ----------------
#define OFF_WF    0                      /* W frags: 4 nt x 32 ks x 256B = 32768 */
#define OFF_GSUM  32768                  /* 2 kh x 64 b x GST x 4B = 20480 */
#define OFF_BIAS  53248                  /* 32*4 */
#define SMEM_TOT  53376

// ---------------- persistent device scratch ----------------
__device__ int      g_marks[Bq * NEV];
__device__ float    g_dt[Bq * NEV];
__device__ float    g_wut[128 * 512 * 8];   // W_U transposed: [k][col][gate(7)+pad]
// A fragments: [parity][((mt*32+ks)*32+lane)*4+rg] u32 words (k-pairs of fp16)
__device__ uint32_t g_afrag[2][4 * 32 * 32 * 4];
__device__ unsigned g_flags[NCTA * 32];   // per-CTA epoch flags, 128B apart

// ---------------- helpers ----------------
__device__ __forceinline__ float sigf(float x) {
    return __fdividef(1.0f, 1.0f + __expf(-x));
}

__device__ __forceinline__ void mma16816(float d[4],
                                         uint32_t a0, uint32_t a1, uint32_t a2, uint32_t a3,
                                         uint32_t b0, uint32_t b1) {
    asm volatile(
        "mma.sync.aligned.m16n8k16.row.col.f32.f16.f16.f32 "
        "{%0,%1,%2,%3}, {%4,%5,%6,%7}, {%8,%9}, {%0,%1,%2,%3};"
        : "+f"(d[0]), "+f"(d[1]), "+f"(d[2]), "+f"(d[3])
        : "r"(a0), "r"(a1), "r"(a2), "r"(a3), "r"(b0), "r"(b1));
}

// Poll the 16 producer CTAs of one 4-kstep group: lane L (<16) spins on flag
// (kh*64 + g*16 + L); __syncwarp orders the acquires before cross-lane A reads.
__device__ __forceinline__ void poll_group(int kh, int g, unsigned t, int lane) {
    if (lane < 16) {
        const unsigned* f = &g_flags[(kh * 64 + g * 16 + lane) * 32];
        unsigned v;
        do {
            asm volatile("ld.acquire.gpu.u32 %0, [%1];" : "=r"(v) : "l"(f) : "memory");
        } while (v < t);
    }
    __syncwarp();
}

// ---------------- prep ----------------
__global__ void prep_kernel(const float* __restrict__ seq,
                            const float* __restrict__ times,
                            const float* __restrict__ W_U)
{
    int tid = blockIdx.x * blockDim.x + threadIdx.x;
    int nt  = gridDim.x * blockDim.x;

    for (int i = tid; i < NCTA * 32; i += nt) g_flags[i] = 0u;

    for (int i = tid; i < Bq * NEV; i += nt) {
        int b = i / NEV;
        int n = i - b * NEV;
        const float* s = seq + (size_t)i * KDIM;
        int m = 0;
        #pragma unroll 4
        for (int k = 0; k < KDIM; k++) if (s[k] > 0.5f) m = k;
        g_marks[i] = m;
        g_dt[i] = times[b * (NEV + 1) + n + 1] - times[b * (NEV + 1) + n];
    }
    // transposed W_U: g_wut[k][col][g] (g=0..6, pad 7)
    for (int i = tid; i < 128 * 512 * 8; i += nt) {
        int k   = i >> 12;
        int rem = i & 4095;
        int col = rem >> 3;
        int g   = rem & 7;
        g_wut[i] = (g < 7) ? W_U[(size_t)k * G7 + g * HDIM + col] : 0.f;
    }
    // zero parity-0 A fragments (h_0 = 0)
    uint32_t* a0 = &g_afrag[0][0];
    for (int i = tid; i < 2 * 4 * 32 * 32 * 4; i += nt) a0[i] = 0u;
}

// ---------------- persistent kernel ----------------
// CTA c owns output cols n=0..27 (gate g=n>>2, state col j0+(n&3)) + lamb (n=28).
// GEMM warp (mt=wid>>1, kh=wid&1): 16 m-rows, 16 ksteps in 4 groups of 4.
// Each warp pipelines per-group: poll 16 producer flags -> A loads -> MMA on the
// group loaded two iterations ago; stragglers overlap compute.
__global__ __launch_bounds__(NTH, 1) void persist_kernel(
    const float* __restrict__ b_U,
    const float* __restrict__ W_V,  const float* __restrict__ b_V,
    const float* __restrict__ W_lamb, const float* __restrict__ b_lamb,
    const float* __restrict__ scale,
    float* __restrict__ out)
{
    extern __shared__ char smem[];
    float* gsum    = (float*)(smem + OFF_GSUM);   // [2 kh][64 b][GST]
    float* bias_sm = (float*)(smem + OFF_BIAS);

    const int tid  = threadIdx.x;
    const int wid  = tid >> 5;
    const int lane = tid & 31;
    const int c    = blockIdx.x;
    const int j0   = c * 4;

    // ---- one-time: W slice -> single fp16 fragments in SMEM (B-frag layout) ----
    for (int idx = tid; idx < 32 * 512; idx += NTH) {
        int n = idx & 31, k = idx >> 5;
        float v = 0.f;
        if (n < 28)       v = W_V[(size_t)k * G7 + (n >> 2) * HDIM + j0 + (n & 3)];
        else if (n == 28) v = W_lamb[k * KDIM + c];
        __half hi = __float2half_rn(v);
        int ntl = n >> 3, ks = k >> 4;
        int lw  = (n & 7) * 4 + ((k & 7) >> 1);
        int rg  = ((k & 15) >= 8) ? 1 : 0;
        int byt = (k & 1) * 2;
        *(unsigned short*)(smem + OFF_WF + (ntl * 32 + ks) * 256 + lw * 8 + rg * 4 + byt) = __half_as_ushort(hi);
    }
    if (tid < 28) {
        int col = (tid >> 2) * HDIM + j0 + (tid & 3);
        bias_sm[tid] = b_U[col] + b_V[col];
    }
    if (tid == 28) bias_sm[28] = b_lamb[c];
    if (tid == 29) bias_sm[29] = scale[c];
    __syncthreads();

    // output views: lamb | CLow | Cbar | delta | OutGate
    const size_t BNK = (size_t)Bq * NEV * KDIM;
    const size_t BNH = (size_t)Bq * NEV * HDIM;
    float* outLamb  = out;
    float* outClow  = out + BNK;
    float* outCbar  = out + BNK + BNH;
    float* outDelta = out + BNK + 2 * BNH;
    float* outO     = out + BNK + 3 * BNH;

    const int mt = wid >> 1;      // m-tile (16 batches)
    const int kh = wid & 1;       // k-half (16 ksteps)
    const int je = tid & 3;       // epilogue: state col
    const int be = tid >> 2;      // epilogue: batch
    const int col = j0 + je;
    float ct_r = 0.f, cbar_r = 0.f;

    // ---- prefetch step-0 epilogue operands ----
    float wu_r[7], dt_r = 0.f;
    {
        int mark = g_marks[be * NEV + 0];
        dt_r = g_dt[be * NEV + 0];
        const float4* wp = (const float4*)&g_wut[((size_t)mark * 512 + col) * 8];
        float4 w0 = __ldg(wp), w1 = __ldg(wp + 1);
        wu_r[0] = w0.x; wu_r[1] = w0.y; wu_r[2] = w0.z; wu_r[3] = w0.w;
        wu_r[4] = w1.x; wu_r[5] = w1.y; wu_r[6] = w1.z;
    }

    for (int t = 0; t <= NEV; t++) {
        const int par = t & 1;
        const unsigned tt = (unsigned)t;

        // ---------------- GEMM: per-group poll -> load -> MMA pipeline ----------------
        float D[4][4];
        #pragma unroll
        for (int n = 0; n < 4; n++) { D[n][0] = 0.f; D[n][1] = 0.f; D[n][2] = 0.f; D[n][3] = 0.f; }

        const uint4* pa = (const uint4*)&g_afrag[par][((mt * 32 + kh * 16) * 32 + lane) * 4];

        uint4 ab[3][4];
        if (t > 0) poll_group(kh, 0, tt, lane);
        #pragma unroll
        for (int i = 0; i < 4; i++) ab[0][i] = __ldcg(pa + i * 32);
        if (t > 0) poll_group(kh, 1, tt, lane);
        #pragma unroll
        for (int i = 0; i < 4; i++) ab[1][i] = __ldcg(pa + (4 + i) * 32);

        #pragma unroll
        for (int grp = 0; grp < 4; grp++) {
            const int cur = grp % 3;
            if (grp < 2) {
                if (t > 0) poll_group(kh, grp + 2, tt, lane);
                const int pf = (grp + 2) % 3;
                #pragma unroll
                for (int i = 0; i < 4; i++)
                    ab[pf][i] = __ldcg(pa + ((grp + 2) * 4 + i) * 32);
            }
            #pragma unroll
            for (int k4 = 0; k4 < 4; k4++) {
                const int ks = kh * 16 + grp * 4 + k4;
                const uint4 a = ab[cur][k4];
                #pragma unroll
                for (int nt = 0; nt < 4; nt++) {
                    uint2 w = *(const uint2*)(smem + OFF_WF + (nt * 32 + ks) * 256 + lane * 8);
                    mma16816(D[nt], a.x, a.y, a.z, a.w, w.x, w.y);
                }
            }
        }

        // ---------------- store D to gsum ----------------
        {
            int b0 = mt * 16 + (lane >> 2);
            int n0 = (lane & 3) * 2;
            #pragma unroll
            for (int nt = 0; nt < 4; nt++) {
                float* p0 = gsum + (kh * 64 + b0) * GST + nt * 8 + n0;
                *(float2*)p0             = make_float2(D[nt][0], D[nt][1]);
                *(float2*)(p0 + 8 * GST) = make_float2(D[nt][2], D[nt][3]);
            }
        }
        __syncthreads();   // sync1: gsum complete; all warps' polls passed (all 128 flags >= t)

        // ---------------- latch lamb gsum value (transcendentals deferred) ----------------
        float ltil = 0.f;
        if (t >= 1 && je == 0)
            ltil = gsum[be * GST + 28] + gsum[(64 + be) * GST + 28] + bias_sm[28];

        // ---------------- epilogue: minimal pre-release chain ----------------
        float cl = 0.f, cbn = 0.f, vd = 0.f, vo = 0.f;
        if (t < NEV) {
            float gg[7];
            #pragma unroll
            for (int g = 0; g < 7; g++) {
                int n = g * 4 + je;
                gg[g] = gsum[be * GST + n] + gsum[(64 + be) * GST + n]
                      + wu_r[g] + bias_sm[n];
            }

            float vi  = sigf(gg[0]);
            float vf  = sigf(gg[1]);
            float viB = sigf(gg[2]);
            float vfB = sigf(gg[3]);
            float vz  = 2.0f * sigf(gg[4]);
            vo  = sigf(gg[5]);
            vd  = (gg[6] > 0.f) ? gg[6] : 0.01f * gg[6];

            cl  = vf * ct_r + vi * vz;
            cbn = vfB * cbar_r + viB * vz;
            float ctn = cbn + (cl - cbn) * __expf(dt_r * vd);
            float htn = vo * (2.0f * sigf(2.0f * ctn) - 1.0f);

            ct_r   = ctn;
            cbar_r = cbn;

            // write h_t as a direct u16 into the A-fragment word
            unsigned short hu = __half_as_ushort(__float2half_rn(htn));
            int p   = 2 * c + (je >> 1);
            int mtb = be >> 4, r = be & 15;
            int ksb = p >> 3;
            int lw  = (r & 7) * 4 + (p & 3);
            int rg  = (r >> 3) + ((p >> 2) & 1) * 2;
            int widx = ((mtb * 32 + ksb) * 32 + lw) * 4 + rg;
            ((unsigned short*)&g_afrag[par ^ 1][widx])[je & 1] = hu;
        }
        __syncthreads();   // sync2: publish h + all gsum reads done (WAR-safe)

        // ---------------- arrive (own flag, no contention) ----------------
        if (t < NEV && tid == 0) {
            asm volatile("st.release.gpu.u32 [%0], %1;"
                         :: "l"(&g_flags[c * 32]), "r"((unsigned)(t + 1)) : "memory");
        }

        // ---------------- deferred lamb math + outputs + prefetch ----------------
        if (t >= 1 && je == 0) {
            float sc = bias_sm[29];
            float x = ltil / sc;
            float sp = fmaxf(x, 0.f) + log1pf(__expf(-fabsf(x)));
            outLamb[((size_t)be * NEV + (t - 1)) * KDIM + c] = sc * sp;
        }

        if (t < NEV) {
            size_t ob = ((size_t)be * NEV + t) * HDIM + col;
            outClow[ob]  = cl;
            outCbar[ob]  = cbn;
            outDelta[ob] = vd;
            outO[ob]     = vo;

            if (t + 1 < NEV) {
                int mark = g_marks[be * NEV + (t + 1)];
                dt_r = g_dt[be * NEV + (t + 1)];
                const float4* wp = (const float4*)&g_wut[((size_t)mark * 512 + col) * 8];
                float4 w0 = __ldg(wp), w1 = __ldg(wp + 1);
                wu_r[0] = w0.x; wu_r[1] = w0.y; wu_r[2] = w0.z; wu_r[3] = w0.w;
                wu_r[4] = w1.x; wu_r[5] = w1.y; wu_r[6] = w1.z;
            }
        }
    }
}

// ---------------- launch ----------------
extern "C" void kernel_launch(void* const* d_in, const int* in_sizes, int n_in,
                              void* d_out, int out_size)
{
    const float* seq    = (const float*)d_in[0];
    const float* times  = (const float*)d_in[1];
    const float* W_U    = (const float*)d_in[2];
    const float* b_U    = (const float*)d_in[3];
    const float* W_V    = (const float*)d_in[4];
    const float* b_V    = (const float*)d_in[5];
    const float* W_lamb = (const float*)d_in[6];
    const float* b_lamb = (const float*)d_in[7];
    const float* scale  = (const float*)d_in[8];
    float* out = (float*)d_out;

    static int attr_done = 0;
    if (!attr_done) {
        cudaFuncSetAttribute(persist_kernel,
                             cudaFuncAttributeMaxDynamicSharedMemorySize, SMEM_TOT);
        attr_done = 1;
    }

    prep_kernel<<<64, 256>>>(seq, times, W_U);
    persist_kernel<<<NCTA, NTH, SMEM_TOT>>>(b_U, W_V, b_V,
                                            W_lamb, b_lamb, scale, out);
}

// round 16
// speedup vs baseline: 2.3538x; 2.3538x over previous
#include <cuda_runtime.h>
#include <cuda_fp16.h>
#include <math.h>
#include <stdint.h>

#define Bq    64
#define NEV   512
#define KDIM  128
#define HDIM  512
#define G7    3584
#define NCTA  128
#define NTH   256
#define GST   40            /* gsum row stride in floats */

// ---------------- SMEM layout (bytes, dynamic) ----------------
#define OFF_WF    0                      /* W frags: 4 nt x 32 ks x 256B = 32768 */
#define OFF_GSUM  32768                  /* 2 kh x 64 b x GST x 4B = 20480 */
#define OFF_BIAS  53248                  /* 32*4 */
#define SMEM_TOT  53376

// ---------------- persistent device scratch ----------------
__device__ int      g_marks[Bq * NEV];
__device__ float    g_dt[Bq * NEV];
__device__ float    g_wut[128 * 512 * 8];   // W_U transposed: [k][col][gate(7)+pad]
// A fragments: [parity][((mt*32+ks)*32+lane)*4+rg] u32 words (k-pairs of fp16)
__device__ uint32_t g_afrag[2][4 * 32 * 32 * 4];
__device__ unsigned g_flags[NCTA * 32];   // per-CTA epoch flags, 128B apart

// ---------------- helpers ----------------
__device__ __forceinline__ float sigf(float x) {
    return __fdividef(1.0f, 1.0f + __expf(-x));
}

__device__ __forceinline__ void mma16816(float d[4],
                                         uint32_t a0, uint32_t a1, uint32_t a2, uint32_t a3,
                                         uint32_t b0, uint32_t b1) {
    asm volatile(
        "mma.sync.aligned.m16n8k16.row.col.f32.f16.f16.f32 "
        "{%0,%1,%2,%3}, {%4,%5,%6,%7}, {%8,%9}, {%0,%1,%2,%3};"
        : "+f"(d[0]), "+f"(d[1]), "+f"(d[2]), "+f"(d[3])
        : "r"(a0), "r"(a1), "r"(a2), "r"(a3), "r"(b0), "r"(b1));
}

// ---------------- prep ----------------
__global__ void prep_kernel(const float* __restrict__ seq,
                            const float* __restrict__ times,
                            const float* __restrict__ W_U)
{
    int tid = blockIdx.x * blockDim.x + threadIdx.x;
    int nt  = gridDim.x * blockDim.x;

    for (int i = tid; i < NCTA * 32; i += nt) g_flags[i] = 0u;

    for (int i = tid; i < Bq * NEV; i += nt) {
        int b = i / NEV;
        int n = i - b * NEV;
        const float* s = seq + (size_t)i * KDIM;
        int m = 0;
        #pragma unroll 4
        for (int k = 0; k < KDIM; k++) if (s[k] > 0.5f) m = k;
        g_marks[i] = m;
        g_dt[i] = times[b * (NEV + 1) + n + 1] - times[b * (NEV + 1) + n];
    }
    // transposed W_U: g_wut[k][col][g] (g=0..6, pad 7)
    for (int i = tid; i < 128 * 512 * 8; i += nt) {
        int k   = i >> 12;
        int rem = i & 4095;
        int col = rem >> 3;
        int g   = rem & 7;
        g_wut[i] = (g < 7) ? W_U[(size_t)k * G7 + g * HDIM + col] : 0.f;
    }
    // zero parity-0 A fragments (h_0 = 0)
    uint32_t* a0 = &g_afrag[0][0];
    for (int i = tid; i < 2 * 4 * 32 * 32 * 4; i += nt) a0[i] = 0u;
}

// ---------------- persistent kernel ----------------
// CTA c owns output cols n=0..27 (gate g=n>>2, state col j0+(n&3)) + lamb (n=28).
// GEMM warp (mt=wid>>1, kh=wid&1): 16 m-rows, 16 ksteps.
// Detection: each warp polls 16 distinct producer flags (one per lane, lane<16),
// ONCE before its GEMM — single L2 round after last arrival, no relay. The 8
// warps jointly cover all 128 flags; sync1 therefore certifies the full epoch.
__global__ __launch_bounds__(NTH, 1) void persist_kernel(
    const float* __restrict__ b_U,
    const float* __restrict__ W_V,  const float* __restrict__ b_V,
    const float* __restrict__ W_lamb, const float* __restrict__ b_lamb,
    const float* __restrict__ scale,
    float* __restrict__ out)
{
    extern __shared__ char smem[];
    float* gsum    = (float*)(smem + OFF_GSUM);   // [2 kh][64 b][GST]
    float* bias_sm = (float*)(smem + OFF_BIAS);

    const int tid  = threadIdx.x;
    const int wid  = tid >> 5;
    const int lane = tid & 31;
    const int c    = blockIdx.x;
    const int j0   = c * 4;

    // ---- one-time: W slice -> single fp16 fragments in SMEM (B-frag layout) ----
    for (int idx = tid; idx < 32 * 512; idx += NTH) {
        int n = idx & 31, k = idx >> 5;
        float v = 0.f;
        if (n < 28)       v = W_V[(size_t)k * G7 + (n >> 2) * HDIM + j0 + (n & 3)];
        else if (n == 28) v = W_lamb[k * KDIM + c];
        __half hi = __float2half_rn(v);
        int ntl = n >> 3, ks = k >> 4;
        int lw  = (n & 7) * 4 + ((k & 7) >> 1);
        int rg  = ((k & 15) >= 8) ? 1 : 0;
        int byt = (k & 1) * 2;
        *(unsigned short*)(smem + OFF_WF + (ntl * 32 + ks) * 256 + lw * 8 + rg * 4 + byt) = __half_as_ushort(hi);
    }
    if (tid < 28) {
        int col = (tid >> 2) * HDIM + j0 + (tid & 3);
        bias_sm[tid] = b_U[col] + b_V[col];
    }
    if (tid == 28) bias_sm[28] = b_lamb[c];
    if (tid == 29) bias_sm[29] = scale[c];
    __syncthreads();

    // output views: lamb | CLow | Cbar | delta | OutGate
    const size_t BNK = (size_t)Bq * NEV * KDIM;
    const size_t BNH = (size_t)Bq * NEV * HDIM;
    float* outLamb  = out;
    float* outClow  = out + BNK;
    float* outCbar  = out + BNK + BNH;
    float* outDelta = out + BNK + 2 * BNH;
    float* outO     = out + BNK + 3 * BNH;

    const int mt = wid >> 1;      // m-tile (16 batches)
    const int kh = wid & 1;       // k-half (16 ksteps)
    const int je = tid & 3;       // epilogue: state col
    const int be = tid >> 2;      // epilogue: batch
    const int col = j0 + je;
    float ct_r = 0.f, cbar_r = 0.f;

    // this warp's 16 flags (one per lane, lane<16): CTAs [wid*16, wid*16+16)
    const unsigned* flp = &g_flags[(wid * 16 + (lane & 15)) * 32];

    // ---- prefetch step-0 epilogue operands ----
    float wu_r[7], dt_r = 0.f;
    {
        int mark = g_marks[be * NEV + 0];
        dt_r = g_dt[be * NEV + 0];
        const float4* wp = (const float4*)&g_wut[((size_t)mark * 512 + col) * 8];
        float4 w0 = __ldg(wp), w1 = __ldg(wp + 1);
        wu_r[0] = w0.x; wu_r[1] = w0.y; wu_r[2] = w0.z; wu_r[3] = w0.w;
        wu_r[4] = w1.x; wu_r[5] = w1.y; wu_r[6] = w1.z;
    }

    for (int t = 0; t <= NEV; t++) {
        const int par = t & 1;

        // ---------------- wait: each warp directly polls its 16 flags (up front) ----------------
        if (t > 0) {
            if (lane < 16) {
                unsigned v;
                do {
                    asm volatile("ld.acquire.gpu.u32 %0, [%1];" : "=r"(v) : "l"(flp) : "memory");
                } while (v < (unsigned)t);
            }
            __syncwarp();
        }

        // ---------------- GEMM: single fp16 A x single fp16 W, triple-buffered A --------
        float D[4][4];
        #pragma unroll
        for (int n = 0; n < 4; n++) { D[n][0] = 0.f; D[n][1] = 0.f; D[n][2] = 0.f; D[n][3] = 0.f; }

        const uint4* pa = (const uint4*)&g_afrag[par][((mt * 32 + kh * 16) * 32 + lane) * 4];

        uint4 ab[3][4];
        #pragma unroll
        for (int i = 0; i < 4; i++) ab[0][i] = __ldcg(pa + i * 32);
        #pragma unroll
        for (int i = 0; i < 4; i++) ab[1][i] = __ldcg(pa + (4 + i) * 32);

        #pragma unroll
        for (int grp = 0; grp < 4; grp++) {
            const int cur = grp % 3;
            if (grp < 2) {
                const int pf = (grp + 2) % 3;
                #pragma unroll
                for (int i = 0; i < 4; i++)
                    ab[pf][i] = __ldcg(pa + ((grp + 2) * 4 + i) * 32);
            }
            #pragma unroll
            for (int k4 = 0; k4 < 4; k4++) {
                const int ks = kh * 16 + grp * 4 + k4;
                const uint4 a = ab[cur][k4];
                #pragma unroll
                for (int nt = 0; nt < 4; nt++) {
                    uint2 w = *(const uint2*)(smem + OFF_WF + (nt * 32 + ks) * 256 + lane * 8);
                    mma16816(D[nt], a.x, a.y, a.z, a.w, w.x, w.y);
                }
            }
        }

        // ---------------- store D to gsum ----------------
        {
            int b0 = mt * 16 + (lane >> 2);
            int n0 = (lane & 3) * 2;
            #pragma unroll
            for (int nt = 0; nt < 4; nt++) {
                float* p0 = gsum + (kh * 64 + b0) * GST + nt * 8 + n0;
                *(float2*)p0             = make_float2(D[nt][0], D[nt][1]);
                *(float2*)(p0 + 8 * GST) = make_float2(D[nt][2], D[nt][3]);
            }
        }
        __syncthreads();   // sync1: gsum complete; 8 warps jointly saw all 128 flags >= t

        // ---------------- latch lamb gsum value (transcendentals deferred) ----------------
        float ltil = 0.f;
        if (t >= 1 && je == 0)
            ltil = gsum[be * GST + 28] + gsum[(64 + be) * GST + 28] + bias_sm[28];

        // ---------------- epilogue: minimal pre-release chain ----------------
        float cl = 0.f, cbn = 0.f, vd = 0.f, vo = 0.f;
        if (t < NEV) {
            float gg[7];
            #pragma unroll
            for (int g = 0; g < 7; g++) {
                int n = g * 4 + je;
                gg[g] = gsum[be * GST + n] + gsum[(64 + be) * GST + n]
                      + wu_r[g] + bias_sm[n];
            }

            float vi  = sigf(gg[0]);
            float vf  = sigf(gg[1]);
            float viB = sigf(gg[2]);
            float vfB = sigf(gg[3]);
            float vz  = 2.0f * sigf(gg[4]);
            vo  = sigf(gg[5]);
            vd  = (gg[6] > 0.f) ? gg[6] : 0.01f * gg[6];

            cl  = vf * ct_r + vi * vz;
            cbn = vfB * cbar_r + viB * vz;
            float ctn = cbn + (cl - cbn) * __expf(dt_r * vd);
            float htn = vo * (2.0f * sigf(2.0f * ctn) - 1.0f);

            ct_r   = ctn;
            cbar_r = cbn;

            // write h_t as a direct u16 into the A-fragment word
            unsigned short hu = __half_as_ushort(__float2half_rn(htn));
            int p   = 2 * c + (je >> 1);
            int mtb = be >> 4, r = be & 15;
            int ksb = p >> 3;
            int lw  = (r & 7) * 4 + (p & 3);
            int rg  = (r >> 3) + ((p >> 2) & 1) * 2;
            int widx = ((mtb * 32 + ksb) * 32 + lw) * 4 + rg;
            ((unsigned short*)&g_afrag[par ^ 1][widx])[je & 1] = hu;
        }
        __syncthreads();   // sync2: publish h + all gsum reads done (WAR-safe)

        // ---------------- arrive (own flag, no contention) ----------------
        if (t < NEV && tid == 0) {
            asm volatile("st.release.gpu.u32 [%0], %1;"
                         :: "l"(&g_flags[c * 32]), "r"((unsigned)(t + 1)) : "memory");
        }

        // ---------------- deferred lamb math + outputs + prefetch ----------------
        if (t >= 1 && je == 0) {
            float sc = bias_sm[29];
            float x = ltil / sc;
            float sp = fmaxf(x, 0.f) + log1pf(__expf(-fabsf(x)));
            outLamb[((size_t)be * NEV + (t - 1)) * KDIM + c] = sc * sp;
        }

        if (t < NEV) {
            size_t ob = ((size_t)be * NEV + t) * HDIM + col;
            outClow[ob]  = cl;
            outCbar[ob]  = cbn;
            outDelta[ob] = vd;
            outO[ob]     = vo;

            if (t + 1 < NEV) {
                int mark = g_marks[be * NEV + (t + 1)];
                dt_r = g_dt[be * NEV + (t + 1)];
                const float4* wp = (const float4*)&g_wut[((size_t)mark * 512 + col) * 8];
                float4 w0 = __ldg(wp), w1 = __ldg(wp + 1);
                wu_r[0] = w0.x; wu_r[1] = w0.y; wu_r[2] = w0.z; wu_r[3] = w0.w;
                wu_r[4] = w1.x; wu_r[5] = w1.y; wu_r[6] = w1.z;
            }
        }
    }
}

// ---------------- launch ----------------
extern "C" void kernel_launch(void* const* d_in, const int* in_sizes, int n_in,
                              void* d_out, int out_size)
{
    const float* seq    = (const float*)d_in[0];
    const float* times  = (const float*)d_in[1];
    const float* W_U    = (const float*)d_in[2];
    const float* b_U    = (const float*)d_in[3];
    const float* W_V    = (const float*)d_in[4];
    const float* b_V    = (const float*)d_in[5];
    const float* W_lamb = (const float*)d_in[6];
    const float* b_lamb = (const float*)d_in[7];
    const float* scale  = (const float*)d_in[8];
    float* out = (float*)d_out;

    static int attr_done = 0;
    if (!attr_done) {
        cudaFuncSetAttribute(persist_kernel,
                             cudaFuncAttributeMaxDynamicSharedMemorySize, SMEM_TOT);
        attr_done = 1;
    }

    prep_kernel<<<64, 256>>>(seq, times, W_U);
    persist_kernel<<<NCTA, NTH, SMEM_TOT>>>(b_U, W_V, b_V,
                                            W_lamb, b_lamb, scale, out);
}